// round 1
// baseline (speedup 1.0000x reference)
#include <cuda_runtime.h>

// Problem constants (fixed by setup_inputs)
#define B_    4
#define C_    256
#define H_    256
#define W_    512
#define FS    14
#define NP    (FS*FS)        // 196
#define NROI  400            // B * MAXLOAD
#define HW    (H_*W_)        // 131072
#define HB    (B_*H_)        // 1024 stacked rows

static const long OUT_MAIN = (long)NROI * C_ * NP;   // 20,070,400

__global__ void pooler_kernel(const float* __restrict__ feat,
                              const float* __restrict__ rois,
                              float* __restrict__ out)
{
    long t = (long)blockIdx.x * blockDim.x + threadIdx.x;
    if (t >= OUT_MAIN) return;

    int  p  = (int)(t % NP);
    long nc = t / NP;
    int  c  = (int)(nc % C_);
    int  n  = (int)(nc / C_);
    int  i  = p / FS;
    int  j  = p % FS;
    int  b  = n / 100;               // batch of this roi

    // roi = (x0, y0, x1, y1)
    const float4 r = reinterpret_cast<const float4*>(rois)[n];
    float scalex = r.z - r.x;
    float scaley = r.w - r.y;
    float biasx  = r.x;
    float biasy  = r.y + (float)b * 1024.0f;   // image_height = 1024

    const float inv13 = 1.0f / 13.0f;          // fs - 1
    float gridx = ((float)j * inv13 * scalex + biasx) * 0.25f;  // /shrink_scale
    float gridy = ((float)i * inv13 * scaley + biasy) * 0.25f;

    // normalized-grid round trip, exactly as reference
    float gx = (gridx * (1.0f / (W_ - 1)) - 0.5f) * 2.0f;
    float gy = (gridy * (1.0f / (HB - 1)) - 0.5f) * 2.0f;
    float px = ((gx + 1.0f) * (float)W_  - 1.0f) * 0.5f;
    float py = ((gy + 1.0f) * (float)HB  - 1.0f) * 0.5f;
    px = fminf(fmaxf(px, 0.0f), (float)(W_ - 1));
    py = fminf(fmaxf(py, 0.0f), (float)(HB - 1));

    float x0f = floorf(px);
    float y0f = floorf(py);
    float wx  = px - x0f;
    float wy  = py - y0f;
    int x0 = (int)x0f;
    int y0 = (int)y0f;
    int x1 = min(x0 + 1, W_ - 1);
    int y1 = min(y0 + 1, HB - 1);

    // feats view: (C, B*H, W); feats[c, y, x] = features[(y>>8), c, y&255, x]
    long a00 = ((long)(y0 >> 8) * C_ + c) * HW + (long)(y0 & 255) * W_;
    long a10 = ((long)(y1 >> 8) * C_ + c) * HW + (long)(y1 & 255) * W_;

    float f00 = __ldg(feat + a00 + x0);
    float f01 = __ldg(feat + a00 + x1);
    float f10 = __ldg(feat + a10 + x0);
    float f11 = __ldg(feat + a10 + x1);

    float omwx = 1.0f - wx;
    float omwy = 1.0f - wy;
    out[t] = f00 * omwx * omwy + f01 * wx * omwy
           + f10 * omwx * wy   + f11 * wx * wy;
}

// Tail: if the harness output also contains val_bind (reference returns a
// tuple), fill out[OUT_MAIN + k] = k / 100  (repeat(arange(B), MAXLOAD)).
__global__ void valbind_tail_kernel(float* __restrict__ out, int tail)
{
    int k = blockIdx.x * blockDim.x + threadIdx.x;
    if (k < tail) {
        out[OUT_MAIN + k] = (float)(k / 100);
    }
}

extern "C" void kernel_launch(void* const* d_in, const int* in_sizes, int n_in,
                              void* d_out, int out_size)
{
    const float* feat = (const float*)d_in[0];
    const float* rois = (const float*)d_in[1];
    float* out = (float*)d_out;

    const int threads = 256;
    long blocks = (OUT_MAIN + threads - 1) / threads;   // 78,400
    pooler_kernel<<<(unsigned)blocks, threads>>>(feat, rois, out);

    long tail = (long)out_size - OUT_MAIN;
    if (tail > 0) {
        int tb = (int)((tail + 127) / 128);
        valbind_tail_kernel<<<tb, 128>>>(out, (int)tail);
    }
}